// round 5
// baseline (speedup 1.0000x reference)
#include <cuda_runtime.h>
#include <cuda_bf16.h>
#include <cstdint>

// ---------------------------------------------------------------------------
// HRR self-attention, restructured:
//   Wf1 = W_qkv folded with forward DFT  -> GEMM1: F = x @ Wf1   (Fq,Fk,Fv, 65 bins, re/im)
//   chunked complex scan: Spec = cumsum_s(Fk*Fv) * conj(Fq)
//   Wf2 = iDFT folded with W_out         -> GEMM2: out = Spec @ Wf2
// All fp32. GEMM inner loop uses packed fma.rn.f32x2 (2 FMA/issue on sm_103a).
// ---------------------------------------------------------------------------

#define BATCH 4
#define SEQ   4096
#define DMODEL 1024
#define NHEAD 8
#define HD    128
#define NF    65          // rfft bins for length-128 real input
#define NROWS (BATCH*SEQ) // 16384
#define NP1   3200        // GEMM1 N: 3*8*65*2 = 3120 padded to 25*128
#define NC1   3120
#define NP2   1152        // GEMM2 K: 8*65*2 = 1040 padded to 9*128
#define NC2   1040
#define CHUNKS 32
#define CLEN   128        // SEQ / CHUNKS

// ---------------- scratch (static device globals; zero-initialized) --------
__device__ float  g_Wf1[(size_t)DMODEL * NP1];       // 13.1 MB
__device__ float  g_Wf2[(size_t)NP2 * DMODEL];       //  4.7 MB
__device__ float  g_F  [(size_t)NROWS * NP1];        // 209.7 MB
__device__ float  g_Spec[(size_t)NROWS * NP2];       //  75.5 MB (pad cols stay 0)
__device__ float2 g_CS [32 * CHUNKS * NF];
__device__ float2 g_Off[32 * CHUNKS * NF];

// ---------------------------------------------------------------------------
// Wf1[d, ((t*8+h)*65+f)*2 + {re,im}]:
//   re = sum_n w_qkv[d, t*1024+h*128+n] * cos(2pi f n/128)
//   im = -sum_n w_qkv[d, ...] * sin(2pi f n/128)
// pad cols [3120,3200) = 0
// ---------------------------------------------------------------------------
__global__ void build_wf1(const float* __restrict__ w_qkv)
{
    __shared__ float sw[3072];
    __shared__ float sc[128];
    __shared__ float ss[128];
    const int d = blockIdx.x;
    const int tid = threadIdx.x;

    for (int i = tid; i < 3072; i += 256)
        sw[i] = w_qkv[(size_t)d * 3072 + i];
    if (tid < 128) {
        float s, c;
        sincosf(6.2831853071795864769f * (float)tid / 128.0f, &s, &c);
        sc[tid] = c; ss[tid] = s;
    }
    __syncthreads();

    for (int p = tid; p < 1600; p += 256) {   // 1600 col-pairs = 3200 cols
        float re = 0.0f, im = 0.0f;
        if (p < 1560) {
            const int t = p / 520;
            const int rem = p % 520;
            const int h = rem / 65;
            const int f = rem % 65;
            const int base = t * 1024 + h * 128;
            int idx = 0;                      // (f*n) mod 128, exact reduction
            #pragma unroll 4
            for (int n = 0; n < 128; ++n) {
                const float w = sw[base + n];
                re += w * sc[idx];
                im -= w * ss[idx];
                idx = (idx + f) & 127;
            }
        }
        g_Wf1[(size_t)d * NP1 + 2 * p]     = re;
        g_Wf1[(size_t)d * NP1 + 2 * p + 1] = im;
    }
}

// ---------------------------------------------------------------------------
// Wf2[(h*65+f)*2+part, d']:
//   part0:  (c_f/128) * sum_n cos(2pi f n/128) * w_out[h*128+n, d']
//   part1: -(c_f/128) * sum_n sin(2pi f n/128) * w_out[h*128+n, d']
//   c_f = 1 for f in {0,64}, else 2  (conjugate-symmetric half-spectrum iDFT)
// pad rows [1040,1152) = 0
// ---------------------------------------------------------------------------
__global__ void build_wf2(const float* __restrict__ w_out)
{
    __shared__ float coef[128];
    const int r = blockIdx.x;
    const int tid = threadIdx.x;

    if (r >= NC2) {
        #pragma unroll
        for (int j = 0; j < 4; ++j)
            g_Wf2[(size_t)r * DMODEL + tid + j * 256] = 0.0f;
        return;
    }
    const int h = r / 130;
    const int rr = r % 130;
    const int f = rr >> 1;
    const int part = rr & 1;

    if (tid < 128) {
        const int m = (f * tid) & 127;
        float s, c;
        sincosf(6.2831853071795864769f * (float)m / 128.0f, &s, &c);
        const float cf = (f == 0 || f == 64) ? 1.0f : 2.0f;
        coef[tid] = part ? (-(cf / 128.0f) * s) : ((cf / 128.0f) * c);
    }
    __syncthreads();

    float acc0 = 0.f, acc1 = 0.f, acc2 = 0.f, acc3 = 0.f;
    for (int n = 0; n < 128; ++n) {
        const float cv = coef[n];
        const float* wp = w_out + (size_t)(h * 128 + n) * DMODEL + tid;
        acc0 += cv * wp[0];
        acc1 += cv * wp[256];
        acc2 += cv * wp[512];
        acc3 += cv * wp[768];
    }
    g_Wf2[(size_t)r * DMODEL + tid]       = acc0;
    g_Wf2[(size_t)r * DMODEL + tid + 256] = acc1;
    g_Wf2[(size_t)r * DMODEL + tid + 512] = acc2;
    g_Wf2[(size_t)r * DMODEL + tid + 768] = acc3;
}

// ---------------------------------------------------------------------------
// SGEMM: C[M,N] = A[M,K] @ B[K,N], row-major, all dims multiples of tile.
// 128x128x16 tiles, 256 threads, 8x8 micro-tile, double-buffered smem,
// packed f32x2 FMA accumulators (2 fp32 FMA per issue slot).
// ---------------------------------------------------------------------------
#define BM 128
#define BN 128
#define BK 16

__global__ __launch_bounds__(256, 2)
void sgemm_f32x2(const float* __restrict__ A, const float* __restrict__ B,
                 float* __restrict__ C, int M, int N, int K)
{
    __shared__ float As[2][BK][BM];
    __shared__ float Bs[2][BK][BN];

    const int tid = threadIdx.x;
    const int tx = tid & 15;
    const int ty = tid >> 4;
    const size_t row0 = (size_t)blockIdx.y * BM;
    const size_t col0 = (size_t)blockIdx.x * BN;

    const int arow = tid >> 2;          // 0..63 (+64)
    const int acol = (tid & 3) << 2;    // 0,4,8,12
    const int brow = tid >> 5;          // 0..7 (+8)
    const int bcol = (tid & 31) << 2;   // 0..124

    const float* Ag = A + row0 * (size_t)K;
    const float* Bg = B + col0;

    unsigned long long acc[8][4];
    #pragma unroll
    for (int i = 0; i < 8; ++i)
        #pragma unroll
        for (int j = 0; j < 4; ++j) acc[i][j] = 0ull;

    const int KT = K / BK;
    float4 pa0, pa1, pb0, pb1;

    // prologue: tile 0 -> buf 0
    pa0 = *(const float4*)(Ag + (size_t)arow * K + acol);
    pa1 = *(const float4*)(Ag + (size_t)(arow + 64) * K + acol);
    pb0 = *(const float4*)(Bg + (size_t)brow * N + bcol);
    pb1 = *(const float4*)(Bg + (size_t)(brow + 8) * N + bcol);
    As[0][acol + 0][arow] = pa0.x;
    As[0][acol + 1][arow] = pa0.y;
    As[0][acol + 2][arow] = pa0.z;
    As[0][acol + 3][arow] = pa0.w;
    As[0][acol + 0][arow + 64] = pa1.x;
    As[0][acol + 1][arow + 64] = pa1.y;
    As[0][acol + 2][arow + 64] = pa1.z;
    As[0][acol + 3][arow + 64] = pa1.w;
    *(float4*)&Bs[0][brow][bcol]     = pb0;
    *(float4*)&Bs[0][brow + 8][bcol] = pb1;
    __syncthreads();

    int cur = 0;
    for (int kt = 0; kt < KT; ++kt) {
        const bool has = (kt + 1) < KT;
        if (has) {
            const int k0 = (kt + 1) * BK;
            pa0 = *(const float4*)(Ag + (size_t)arow * K + k0 + acol);
            pa1 = *(const float4*)(Ag + (size_t)(arow + 64) * K + k0 + acol);
            pb0 = *(const float4*)(Bg + (size_t)(k0 + brow) * N + bcol);
            pb1 = *(const float4*)(Bg + (size_t)(k0 + brow + 8) * N + bcol);
        }

        #pragma unroll
        for (int kk = 0; kk < BK; ++kk) {
            float a[8];
            *(float4*)&a[0] = *(const float4*)&As[cur][kk][ty * 8];
            *(float4*)&a[4] = *(const float4*)&As[cur][kk][ty * 8 + 4];
            unsigned long long bp[4];
            const unsigned long long* bq =
                (const unsigned long long*)&Bs[cur][kk][tx * 8];
            bp[0] = bq[0]; bp[1] = bq[1]; bp[2] = bq[2]; bp[3] = bq[3];
            #pragma unroll
            for (int i = 0; i < 8; ++i) {
                unsigned long long ap;
                const unsigned int ai = __float_as_uint(a[i]);
                asm("mov.b64 %0, {%1, %2};" : "=l"(ap) : "r"(ai), "r"(ai));
                #pragma unroll
                for (int j = 0; j < 4; ++j)
                    asm("fma.rn.f32x2 %0, %1, %2, %0;"
                        : "+l"(acc[i][j]) : "l"(ap), "l"(bp[j]));
            }
        }

        if (has) {
            const int nxt = cur ^ 1;
            As[nxt][acol + 0][arow] = pa0.x;
            As[nxt][acol + 1][arow] = pa0.y;
            As[nxt][acol + 2][arow] = pa0.z;
            As[nxt][acol + 3][arow] = pa0.w;
            As[nxt][acol + 0][arow + 64] = pa1.x;
            As[nxt][acol + 1][arow + 64] = pa1.y;
            As[nxt][acol + 2][arow + 64] = pa1.z;
            As[nxt][acol + 3][arow + 64] = pa1.w;
            *(float4*)&Bs[nxt][brow][bcol]     = pb0;
            *(float4*)&Bs[nxt][brow + 8][bcol] = pb1;
            __syncthreads();
            cur = nxt;
        }
    }

    float* Cp = C + (row0 + (size_t)ty * 8) * N + col0 + tx * 8;
    #pragma unroll
    for (int i = 0; i < 8; ++i) {
        float o[8];
        #pragma unroll
        for (int j = 0; j < 4; ++j) {
            unsigned int lo, hi;
            asm("mov.b64 {%0, %1}, %2;" : "=r"(lo), "=r"(hi) : "l"(acc[i][j]));
            o[2 * j]     = __uint_as_float(lo);
            o[2 * j + 1] = __uint_as_float(hi);
        }
        *(float4*)(Cp + (size_t)i * N)     = make_float4(o[0], o[1], o[2], o[3]);
        *(float4*)(Cp + (size_t)i * N + 4) = make_float4(o[4], o[5], o[6], o[7]);
    }
}

// ---------------------------------------------------------------------------
// Chunked complex prefix scan of Fk*Fv over s, then Spec = cumsum * conj(Fq).
// g_F col layout per row: [(t*8+h)*65+f]*2 + part ; q@0, k@1040, v@2080 base.
// ---------------------------------------------------------------------------
__global__ void chunk_sum_kernel()
{
    const int c  = blockIdx.x;
    const int bh = blockIdx.y;
    const int f  = threadIdx.x;              // 0..64
    const int b = bh >> 3, h = bh & 7;
    const size_t rowbase = ((size_t)b * SEQ + (size_t)c * CLEN) * NP1;
    const int kc = 1040 + h * 130 + 2 * f;
    const int vc = 2080 + h * 130 + 2 * f;
    float sr = 0.f, si = 0.f;
    for (int s = 0; s < CLEN; ++s) {
        const float* p = g_F + rowbase + (size_t)s * NP1;
        const float2 K2 = *(const float2*)(p + kc);
        const float2 V2 = *(const float2*)(p + vc);
        sr += K2.x * V2.x - K2.y * V2.y;
        si += K2.x * V2.y + K2.y * V2.x;
    }
    g_CS[(bh * CHUNKS + c) * NF + f] = make_float2(sr, si);
}

__global__ void scan_off_kernel()
{
    const int bh = blockIdx.x;
    const int f  = threadIdx.x;
    float rr = 0.f, ri = 0.f;
    for (int c = 0; c < CHUNKS; ++c) {
        const int idx = (bh * CHUNKS + c) * NF + f;
        g_Off[idx] = make_float2(rr, ri);
        const float2 v = g_CS[idx];
        rr += v.x; ri += v.y;
    }
}

__global__ void spec_kernel()
{
    const int c  = blockIdx.x;
    const int bh = blockIdx.y;
    const int tid = threadIdx.x;
    const int b = bh >> 3, h = bh & 7;
    const size_t rbF = ((size_t)b * SEQ + (size_t)c * CLEN) * NP1;
    const size_t rbS = ((size_t)b * SEQ + (size_t)c * CLEN) * NP2;

    if (tid < NF) {
        const int f = tid;
        const int qc = h * 130 + 2 * f;
        const int kc = 1040 + qc;
        const int vc = 2080 + qc;
        float2 acc = g_Off[(bh * CHUNKS + c) * NF + f];
        for (int s = 0; s < CLEN; ++s) {
            const float* p = g_F + rbF + (size_t)s * NP1;
            const float2 K2 = *(const float2*)(p + kc);
            const float2 V2 = *(const float2*)(p + vc);
            const float2 Q2 = *(const float2*)(p + qc);
            acc.x += K2.x * V2.x - K2.y * V2.y;
            acc.y += K2.x * V2.y + K2.y * V2.x;
            float2 sp;                       // acc * conj(Q)
            sp.x = acc.x * Q2.x + acc.y * Q2.y;
            sp.y = acc.y * Q2.x - acc.x * Q2.y;
            *(float2*)(g_Spec + rbS + (size_t)s * NP2 + qc) = sp;
        }
    } else if (tid < NF + 56) {
        // keep GEMM2 K-pad columns [1040,1152) at finite zero
        const int t = tid - NF;              // 0..55
        for (int s = 0; s < CLEN; ++s)
            *(float2*)(g_Spec + rbS + (size_t)s * NP2 + NC2 + 2 * t) =
                make_float2(0.f, 0.f);
    }
}

// ---------------------------------------------------------------------------
extern "C" void kernel_launch(void* const* d_in, const int* in_sizes, int n_in,
                              void* d_out, int out_size)
{
    const float* x     = (const float*)d_in[0];
    const float* w_qkv = (const float*)d_in[1];
    const float* w_out = (const float*)d_in[2];
    float* out = (float*)d_out;

    float *pWf1, *pWf2, *pF, *pSpec;
    cudaGetSymbolAddress((void**)&pWf1,  g_Wf1);
    cudaGetSymbolAddress((void**)&pWf2,  g_Wf2);
    cudaGetSymbolAddress((void**)&pF,    g_F);
    cudaGetSymbolAddress((void**)&pSpec, g_Spec);

    build_wf1<<<DMODEL, 256>>>(w_qkv);
    build_wf2<<<NP2, 256>>>(w_out);

    {   // GEMM1: F = x @ Wf1   (16384 x 3200 x 1024)
        dim3 grid(NP1 / BN, NROWS / BM);
        sgemm_f32x2<<<grid, 256>>>(x, pWf1, pF, NROWS, NP1, DMODEL);
    }

    chunk_sum_kernel<<<dim3(CHUNKS, 32), NF>>>();
    scan_off_kernel<<<32, NF>>>();
    spec_kernel<<<dim3(CHUNKS, 32), 128>>>();

    {   // GEMM2: out = Spec @ Wf2  (16384 x 1024 x 1152)
        dim3 grid(DMODEL / BN, NROWS / BM);
        sgemm_f32x2<<<grid, 256>>>(pSpec, pWf2, out, NROWS, DMODEL, NP2);
    }
}

// round 7
// speedup vs baseline: 2.0157x; 2.0157x over previous
#include <cuda_runtime.h>
#include <cuda_bf16.h>
#include <cstdint>

// ---------------------------------------------------------------------------
// HRR self-attention:
//   GEMM1 (mma.sync bf16 x3-split): F = x @ (W_qkv . DFT)   [fp32 out]
//   chunked complex scan: Spec = cumsum_s(Fk*Fv) * conj(Fq) -> bf16 split A2
//   GEMM2 (mma.sync bf16 x3-split): out = Spec @ (iDFT . W_out)
// tcgen05 is unavailable (harness PTX pass targets base sm_103, no 'a'
// feature set) -> use HMMA via mma.sync m16n8k16 bf16.
// ---------------------------------------------------------------------------

#define BATCH 4
#define SEQ   4096
#define DMODEL 1024
#define NHEAD 8
#define NF    65
#define NROWS 16384
#define NP1   3328          // GEMM1 N (3120 used, padded to 26*128)
#define KA1   3072          // GEMM1 K' = 3*1024
#define KA2   3456          // GEMM2 K' = 3*1152
#define NPAD2 1152
#define NC2   1040
#define CHUNKS 32
#define CLEN   128

// ---------------- scratch (static device globals; zero-initialized) --------
__device__ __align__(16) float  g_Wf1[(size_t)DMODEL * NP1];
__device__ __align__(16) float  g_Wf2[(size_t)NPAD2 * DMODEL];
__device__ __align__(16) float  g_F  [(size_t)NROWS * NP1];
__device__ __align__(16) __nv_bfloat16 g_A1[(size_t)NROWS * KA1];
__device__ __align__(16) __nv_bfloat16 g_B1[(size_t)NP1   * KA1];
__device__ __align__(16) __nv_bfloat16 g_A2[(size_t)NROWS * KA2];
__device__ __align__(16) __nv_bfloat16 g_B2[(size_t)DMODEL * KA2];
__device__ float2 g_CS [32 * CHUNKS * NF];
__device__ float2 g_Off[32 * CHUNKS * NF];

// ---------------- helpers ---------------------------------------------------
__device__ __forceinline__ uint32_t smem_u32(const void* p) {
    uint32_t a;
    asm("{ .reg .u64 t; cvta.to.shared.u64 t, %1; cvt.u32.u64 %0, t; }"
        : "=r"(a) : "l"(p));
    return a;
}
__device__ __forceinline__ void cp16(uint32_t dst, const void* src) {
    asm volatile("cp.async.cg.shared.global [%0], [%1], 16;"
                 :: "r"(dst), "l"(src) : "memory");
}
__device__ __forceinline__ void ldmx4(uint32_t& r0, uint32_t& r1,
                                      uint32_t& r2, uint32_t& r3, uint32_t a) {
    asm volatile("ldmatrix.sync.aligned.m8n8.x4.shared.b16 {%0,%1,%2,%3}, [%4];"
                 : "=r"(r0), "=r"(r1), "=r"(r2), "=r"(r3) : "r"(a));
}
__device__ __forceinline__ void mma16816(float* c, const uint32_t* a,
                                         const uint32_t* b) {
    asm volatile(
        "mma.sync.aligned.m16n8k16.row.col.f32.bf16.bf16.f32 "
        "{%0,%1,%2,%3}, {%4,%5,%6,%7}, {%8,%9}, {%0,%1,%2,%3};"
        : "+f"(c[0]), "+f"(c[1]), "+f"(c[2]), "+f"(c[3])
        : "r"(a[0]), "r"(a[1]), "r"(a[2]), "r"(a[3]), "r"(b[0]), "r"(b[1]));
}

// ---------------------------------------------------------------------------
// split x -> A1 = [x_hi | x_hi | x_lo]  (pairs with B1 = [W_hi | W_lo | W_hi])
// ---------------------------------------------------------------------------
__global__ void split_x(const float* __restrict__ x, __nv_bfloat16* __restrict__ A1)
{
    const size_t p = (size_t)blockIdx.x * 256 + threadIdx.x;   // < 16384*512
    const size_t row = p >> 9;
    const int dp = (int)(p & 511);
    const float2 v = *(const float2*)(x + row * 1024 + 2 * dp);
    __nv_bfloat162 h2, l2;
    h2.x = __float2bfloat16(v.x);
    h2.y = __float2bfloat16(v.y);
    l2.x = __float2bfloat16(v.x - __bfloat162float(h2.x));
    l2.y = __float2bfloat16(v.y - __bfloat162float(h2.y));
    __nv_bfloat16* base = A1 + row * KA1 + 2 * dp;
    *(__nv_bfloat162*)(base)        = h2;
    *(__nv_bfloat162*)(base + 1024) = h2;
    *(__nv_bfloat162*)(base + 2048) = l2;
}

// ---------------------------------------------------------------------------
// Wf1[d, col]  col = ((t*8+h)*65+f)*2 + {re,im}; pad cols [3120,3328) = 0
// ---------------------------------------------------------------------------
__global__ void build_wf1(const float* __restrict__ w_qkv)
{
    __shared__ float sw[3072];
    __shared__ float sc[128];
    __shared__ float ss[128];
    const int d = blockIdx.x;
    const int tid = threadIdx.x;

    for (int i = tid; i < 3072; i += 256)
        sw[i] = w_qkv[(size_t)d * 3072 + i];
    if (tid < 128) {
        float s, c;
        sincosf(6.2831853071795864769f * (float)tid / 128.0f, &s, &c);
        sc[tid] = c; ss[tid] = s;
    }
    __syncthreads();

    for (int p = tid; p < NP1 / 2; p += 256) {
        float re = 0.0f, im = 0.0f;
        if (p < 1560) {
            const int t = p / 520;
            const int rem = p % 520;
            const int h = rem / 65;
            const int f = rem % 65;
            const int base = t * 1024 + h * 128;
            int idx = 0;
            #pragma unroll 4
            for (int n = 0; n < 128; ++n) {
                const float w = sw[base + n];
                re += w * sc[idx];
                im -= w * ss[idx];
                idx = (idx + f) & 127;
            }
        }
        g_Wf1[(size_t)d * NP1 + 2 * p]     = re;
        g_Wf1[(size_t)d * NP1 + 2 * p + 1] = im;
    }
}

// ---------------------------------------------------------------------------
// Wf2[r, d'] (r < 1040), pad rows [1040,1152) = 0
// ---------------------------------------------------------------------------
__global__ void build_wf2(const float* __restrict__ w_out)
{
    __shared__ float coef[128];
    const int r = blockIdx.x;
    const int tid = threadIdx.x;

    if (r >= NC2) {
        #pragma unroll
        for (int j = 0; j < 4; ++j)
            g_Wf2[(size_t)r * DMODEL + tid + j * 256] = 0.0f;
        return;
    }
    const int h = r / 130;
    const int rr = r % 130;
    const int f = rr >> 1;
    const int part = rr & 1;

    if (tid < 128) {
        const int m = (f * tid) & 127;
        float s, c;
        sincosf(6.2831853071795864769f * (float)m / 128.0f, &s, &c);
        const float cf = (f == 0 || f == 64) ? 1.0f : 2.0f;
        coef[tid] = part ? (-(cf / 128.0f) * s) : ((cf / 128.0f) * c);
    }
    __syncthreads();

    float acc0 = 0.f, acc1 = 0.f, acc2 = 0.f, acc3 = 0.f;
    for (int n = 0; n < 128; ++n) {
        const float cv = coef[n];
        const float* wp = w_out + (size_t)(h * 128 + n) * DMODEL + tid;
        acc0 += cv * wp[0];
        acc1 += cv * wp[256];
        acc2 += cv * wp[512];
        acc3 += cv * wp[768];
    }
    g_Wf2[(size_t)r * DMODEL + tid]       = acc0;
    g_Wf2[(size_t)r * DMODEL + tid + 256] = acc1;
    g_Wf2[(size_t)r * DMODEL + tid + 512] = acc2;
    g_Wf2[(size_t)r * DMODEL + tid + 768] = acc3;
}

// ---------------------------------------------------------------------------
// transpose + bf16 split: src[R][C] fp32 -> dst[C][3R] = [hi | lo | hi]
// ---------------------------------------------------------------------------
__global__ void tsplit(const float* __restrict__ src, __nv_bfloat16* __restrict__ dst,
                       int R, int C)
{
    __shared__ float t[32][33];
    const int c0 = blockIdx.x * 32, r0 = blockIdx.y * 32;
    const int x = threadIdx.x, y = threadIdx.y;
    #pragma unroll
    for (int j = 0; j < 4; ++j)
        t[y + j * 8][x] = src[(size_t)(r0 + y + j * 8) * C + c0 + x];
    __syncthreads();
    #pragma unroll
    for (int j = 0; j < 4; ++j) {
        const int n = c0 + y + j * 8;
        const float v = t[x][y + j * 8];
        const __nv_bfloat16 h = __float2bfloat16(v);
        const __nv_bfloat16 l = __float2bfloat16(v - __bfloat162float(h));
        __nv_bfloat16* dp = dst + (size_t)n * (3 * R) + r0 + x;
        dp[0]     = h;
        dp[R]     = l;
        dp[2 * R] = h;
    }
}

// ---------------------------------------------------------------------------
// bf16 GEMM via mma.sync m16n8k16: C[M,N] = A[M,K] @ B[N,K]^T, fp32 out.
// BM=256, BN=128, BK=32, 512 threads (16 warps = 4m x 4n, warp tile 64x32),
// 4-stage cp.async pipeline, 80B-padded smem rows (ldmatrix conflict-free).
// ---------------------------------------------------------------------------
#define BM 256
#define BN 128
#define BK 32
#define GSTAGES 4
#define SROW 80                       // bytes per smem row (40 bf16)
#define A_ST_B (BM * SROW)            // 20480
#define B_ST_B (BN * SROW)            // 10240
#define STG_B  (A_ST_B + B_ST_B)      // 30720
#define GSMEM  (GSTAGES * STG_B)      // 122880

__global__ __launch_bounds__(512, 1)
void gemm_mma(const __nv_bfloat16* __restrict__ A,
              const __nv_bfloat16* __restrict__ B,
              float* __restrict__ C, int N, int K, int KT)
{
    extern __shared__ char smem[];
    const uint32_t sb = smem_u32(smem);

    const int tid  = threadIdx.x;
    const int warp = tid >> 5, lane = tid & 31;
    const int wm = warp >> 2, wn = warp & 3;        // 4x4 warp grid
    const size_t row0 = (size_t)blockIdx.y * BM;
    const size_t col0 = (size_t)blockIdx.x * BN;
    const __nv_bfloat16* Ag = A + row0 * (size_t)K;
    const __nv_bfloat16* Bg = B + col0 * (size_t)K;

    // per-thread cp.async mapping
    const int ar0 = tid >> 2;            // A rows tid>>2 and +128
    const int ac  = (tid & 3) * 8;       // element offset within 32-elem chunk
    const int br0 = tid >> 2;            // B row (only tid<512 -> 128 rows x4)

    float acc[4][4][4];
    #pragma unroll
    for (int i = 0; i < 4; ++i)
        #pragma unroll
        for (int j = 0; j < 4; ++j)
            #pragma unroll
            for (int q = 0; q < 4; ++q) acc[i][j][q] = 0.f;

    // prologue: stages 0..GSTAGES-2
    #pragma unroll
    for (int pc = 0; pc < GSTAGES - 1; ++pc) {
        const uint32_t st = sb + pc * STG_B;
        const int kc = pc * BK;
        cp16(st + ar0 * SROW + ac * 2,           Ag + (size_t)ar0 * K + kc + ac);
        cp16(st + (ar0 + 128) * SROW + ac * 2,   Ag + (size_t)(ar0 + 128) * K + kc + ac);
        if (br0 < BN)
            cp16(st + A_ST_B + br0 * SROW + ac * 2, Bg + (size_t)br0 * K + kc + ac);
        asm volatile("cp.async.commit_group;" ::: "memory");
    }

    // ldmatrix per-warp base addresses
    // A frag (m-tile i): row = wm*64 + i*16 + (lane&15), kk = st*16 + (lane>>4)*8
    const uint32_t a_row = (uint32_t)(wm * 64 + (lane & 15));
    const uint32_t a_kk  = (uint32_t)((lane >> 4) * 8);
    // B pair p (n-tiles 2p,2p+1): q=lane>>3; n = wn*32+(2p+(q>>1))*8+(lane&7), kk=st*16+(q&1)*8
    const int q4 = lane >> 3;
    const uint32_t b_row = (uint32_t)(wn * 32 + (q4 >> 1) * 8 + (lane & 7));
    const uint32_t b_kk  = (uint32_t)((q4 & 1) * 8);

    for (int c = 0; c < KT; ++c) {
        const uint32_t st = sb + (c % GSTAGES) * STG_B;
        asm volatile("cp.async.wait_group %0;" :: "n"(GSTAGES - 2) : "memory");
        __syncthreads();

        const int lc = c + GSTAGES - 1;
        if (lc < KT) {
            const uint32_t stn = sb + (lc % GSTAGES) * STG_B;
            const int kc = lc * BK;
            cp16(stn + ar0 * SROW + ac * 2,          Ag + (size_t)ar0 * K + kc + ac);
            cp16(stn + (ar0 + 128) * SROW + ac * 2,  Ag + (size_t)(ar0 + 128) * K + kc + ac);
            if (br0 < BN)
                cp16(stn + A_ST_B + br0 * SROW + ac * 2, Bg + (size_t)br0 * K + kc + ac);
        }
        asm volatile("cp.async.commit_group;" ::: "memory");

        #pragma unroll
        for (int kst = 0; kst < 2; ++kst) {
            uint32_t a[4][4], b[8];
            #pragma unroll
            for (int i = 0; i < 4; ++i)
                ldmx4(a[i][0], a[i][1], a[i][2], a[i][3],
                      st + (a_row + i * 16) * SROW + (kst * 16 + a_kk) * 2);
            #pragma unroll
            for (int p = 0; p < 2; ++p)
                ldmx4(b[4 * p], b[4 * p + 1], b[4 * p + 2], b[4 * p + 3],
                      st + A_ST_B + (b_row + p * 16) * SROW + (kst * 16 + b_kk) * 2);
            #pragma unroll
            for (int i = 0; i < 4; ++i)
                #pragma unroll
                for (int j = 0; j < 4; ++j)
                    mma16816(acc[i][j], a[i], &b[2 * j]);
        }
    }

    // epilogue: direct fp32 stores
    #pragma unroll
    for (int i = 0; i < 4; ++i) {
        const size_t r = row0 + wm * 64 + i * 16 + (lane >> 2);
        #pragma unroll
        for (int j = 0; j < 4; ++j) {
            const size_t cc = col0 + wn * 32 + j * 8 + (lane & 3) * 2;
            *(float2*)(C + r * N + cc)       = make_float2(acc[i][j][0], acc[i][j][1]);
            *(float2*)(C + (r + 8) * N + cc) = make_float2(acc[i][j][2], acc[i][j][3]);
        }
    }
}

// ---------------------------------------------------------------------------
// Chunked complex prefix scan; spec writes bf16-split A2 = [hi | hi | lo]
// g_F col layout: q base 0, k base 1040, v base 2080 (stride NP1)
// ---------------------------------------------------------------------------
__global__ void chunk_sum_kernel()
{
    const int c  = blockIdx.x;
    const int bh = blockIdx.y;
    const int f  = threadIdx.x;
    const int b = bh >> 3, h = bh & 7;
    const size_t rowbase = ((size_t)b * SEQ + (size_t)c * CLEN) * NP1;
    const int kc = 1040 + h * 130 + 2 * f;
    const int vc = 2080 + h * 130 + 2 * f;
    float sr = 0.f, si = 0.f;
    for (int s = 0; s < CLEN; ++s) {
        const float* p = g_F + rowbase + (size_t)s * NP1;
        const float2 Kv = *(const float2*)(p + kc);
        const float2 Vv = *(const float2*)(p + vc);
        sr += Kv.x * Vv.x - Kv.y * Vv.y;
        si += Kv.x * Vv.y + Kv.y * Vv.x;
    }
    g_CS[(bh * CHUNKS + c) * NF + f] = make_float2(sr, si);
}

__global__ void scan_off_kernel()
{
    const int bh = blockIdx.x;
    const int f  = threadIdx.x;
    float rr = 0.f, ri = 0.f;
    for (int c = 0; c < CHUNKS; ++c) {
        const int idx = (bh * CHUNKS + c) * NF + f;
        g_Off[idx] = make_float2(rr, ri);
        const float2 v = g_CS[idx];
        rr += v.x; ri += v.y;
    }
}

__global__ void spec_kernel()
{
    const int c  = blockIdx.x;
    const int bh = blockIdx.y;
    const int f  = threadIdx.x;              // 0..64
    const int b = bh >> 3, h = bh & 7;
    const size_t rbF = ((size_t)b * SEQ + (size_t)c * CLEN) * NP1;
    const size_t rbA = ((size_t)b * SEQ + (size_t)c * CLEN) * KA2;
    const int qc = h * 130 + 2 * f;
    const int kc = 1040 + qc;
    const int vc = 2080 + qc;
    float2 acc = g_Off[(bh * CHUNKS + c) * NF + f];
    for (int s = 0; s < CLEN; ++s) {
        const float* p = g_F + rbF + (size_t)s * NP1;
        const float2 Kv = *(const float2*)(p + kc);
        const float2 Vv = *(const float2*)(p + vc);
        const float2 Qv = *(const float2*)(p + qc);
        acc.x += Kv.x * Vv.x - Kv.y * Vv.y;
        acc.y += Kv.x * Vv.y + Kv.y * Vv.x;
        const float sx = acc.x * Qv.x + acc.y * Qv.y;   // acc * conj(Q)
        const float sy = acc.y * Qv.x - acc.x * Qv.y;
        __nv_bfloat162 h2, l2;
        h2.x = __float2bfloat16(sx);
        h2.y = __float2bfloat16(sy);
        l2.x = __float2bfloat16(sx - __bfloat162float(h2.x));
        l2.y = __float2bfloat16(sy - __bfloat162float(h2.y));
        __nv_bfloat16* dst = g_A2 + rbA + (size_t)s * KA2 + qc;
        *(__nv_bfloat162*)(dst)        = h2;
        *(__nv_bfloat162*)(dst + 1152) = h2;
        *(__nv_bfloat162*)(dst + 2304) = l2;
    }
}

// ---------------------------------------------------------------------------
extern "C" void kernel_launch(void* const* d_in, const int* in_sizes, int n_in,
                              void* d_out, int out_size)
{
    const float* x     = (const float*)d_in[0];
    const float* w_qkv = (const float*)d_in[1];
    const float* w_out = (const float*)d_in[2];
    float* out = (float*)d_out;

    float *pWf1, *pWf2, *pF;
    __nv_bfloat16 *pA1, *pB1, *pA2, *pB2;
    cudaGetSymbolAddress((void**)&pWf1, g_Wf1);
    cudaGetSymbolAddress((void**)&pWf2, g_Wf2);
    cudaGetSymbolAddress((void**)&pF,   g_F);
    cudaGetSymbolAddress((void**)&pA1,  g_A1);
    cudaGetSymbolAddress((void**)&pB1,  g_B1);
    cudaGetSymbolAddress((void**)&pA2,  g_A2);
    cudaGetSymbolAddress((void**)&pB2,  g_B2);

    cudaFuncSetAttribute(gemm_mma, cudaFuncAttributeMaxDynamicSharedMemorySize,
                         GSMEM);

    split_x<<<32768, 256>>>(x, pA1);
    build_wf1<<<DMODEL, 256>>>(w_qkv);
    build_wf2<<<NPAD2, 256>>>(w_out);
    tsplit<<<dim3(NP1 / 32, DMODEL / 32), dim3(32, 8)>>>(pWf1, pB1, DMODEL, NP1);
    tsplit<<<dim3(DMODEL / 32, NPAD2 / 32), dim3(32, 8)>>>(pWf2, pB2, NPAD2, DMODEL);

    // GEMM1: F = x' @ Wf1'^T   (16384 x 3328, K'=3072)
    gemm_mma<<<dim3(NP1 / BN, NROWS / BM), 512, GSMEM>>>(
        pA1, pB1, pF, NP1, KA1, KA1 / BK);

    chunk_sum_kernel<<<dim3(CHUNKS, 32), NF>>>();
    scan_off_kernel<<<32, NF>>>();
    spec_kernel<<<dim3(CHUNKS, 32), NF>>>();

    // GEMM2: out = Spec' @ Wf2'^T   (16384 x 1024, K'=3456)
    gemm_mma<<<dim3(DMODEL / BN, NROWS / BM), 512, GSMEM>>>(
        pA2, pB2, out, DMODEL, KA2, KA2 / BK);
}

// round 8
// speedup vs baseline: 2.0179x; 1.0011x over previous
#include <cuda_runtime.h>
#include <cuda_bf16.h>
#include <cstdint>

// ---------------------------------------------------------------------------
// HRR self-attention:
//   GEMM1 (mma.sync bf16 x3-split): F = x @ (W_qkv . DFT)   [fp32 out]
//   chunked complex scan: Spec = cumsum_s(Fk*Fv) * conj(Fq) -> bf16 split A2
//   GEMM2 (mma.sync bf16 x3-split): out = Spec @ (iDFT . W_out)
// tcgen05 is unavailable (harness PTX pass targets base sm_103, no 'a'
// feature set) -> use HMMA via mma.sync m16n8k16 bf16.
// ---------------------------------------------------------------------------

#define BATCH 4
#define SEQ   4096
#define DMODEL 1024
#define NHEAD 8
#define NF    65
#define NROWS 16384
#define NP1   3328          // GEMM1 N (3120 used, padded to 26*128)
#define KA1   3072          // GEMM1 K' = 3*1024
#define KA2   3456          // GEMM2 K' = 3*1152
#define NPAD2 1152
#define NC2   1040
#define CHUNKS 32
#define CLEN   128

// ---------------- scratch (static device globals; zero-initialized) --------
__device__ __align__(16) float  g_Wf1[(size_t)DMODEL * NP1];
__device__ __align__(16) float  g_Wf2[(size_t)NPAD2 * DMODEL];
__device__ __align__(16) float  g_F  [(size_t)NROWS * NP1];
__device__ __align__(16) __nv_bfloat16 g_A1[(size_t)NROWS * KA1];
__device__ __align__(16) __nv_bfloat16 g_B1[(size_t)NP1   * KA1];
__device__ __align__(16) __nv_bfloat16 g_A2[(size_t)NROWS * KA2];
__device__ __align__(16) __nv_bfloat16 g_B2[(size_t)DMODEL * KA2];
__device__ float2 g_CS [32 * CHUNKS * NF];
__device__ float2 g_Off[32 * CHUNKS * NF];

// ---------------- helpers ---------------------------------------------------
__device__ __forceinline__ uint32_t smem_u32(const void* p) {
    uint32_t a;
    asm("{ .reg .u64 t; cvta.to.shared.u64 t, %1; cvt.u32.u64 %0, t; }"
        : "=r"(a) : "l"(p));
    return a;
}
__device__ __forceinline__ void cp16(uint32_t dst, const void* src) {
    asm volatile("cp.async.cg.shared.global [%0], [%1], 16;"
                 :: "r"(dst), "l"(src) : "memory");
}
__device__ __forceinline__ void ldmx4(uint32_t& r0, uint32_t& r1,
                                      uint32_t& r2, uint32_t& r3, uint32_t a) {
    asm volatile("ldmatrix.sync.aligned.m8n8.x4.shared.b16 {%0,%1,%2,%3}, [%4];"
                 : "=r"(r0), "=r"(r1), "=r"(r2), "=r"(r3) : "r"(a));
}
__device__ __forceinline__ void mma16816(float* c, const uint32_t* a,
                                         const uint32_t* b) {
    asm volatile(
        "mma.sync.aligned.m16n8k16.row.col.f32.bf16.bf16.f32 "
        "{%0,%1,%2,%3}, {%4,%5,%6,%7}, {%8,%9}, {%0,%1,%2,%3};"
        : "+f"(c[0]), "+f"(c[1]), "+f"(c[2]), "+f"(c[3])
        : "r"(a[0]), "r"(a[1]), "r"(a[2]), "r"(a[3]), "r"(b[0]), "r"(b[1]));
}

// ---------------------------------------------------------------------------
// split x -> A1 = [x_hi | x_hi | x_lo]  (pairs with B1 = [W_hi | W_lo | W_hi])
// ---------------------------------------------------------------------------
__global__ void split_x(const float* __restrict__ x, __nv_bfloat16* __restrict__ A1)
{
    const size_t p = (size_t)blockIdx.x * 256 + threadIdx.x;   // < 16384*512
    const size_t row = p >> 9;
    const int dp = (int)(p & 511);
    const float2 v = *(const float2*)(x + row * 1024 + 2 * dp);
    __nv_bfloat162 h2, l2;
    h2.x = __float2bfloat16(v.x);
    h2.y = __float2bfloat16(v.y);
    l2.x = __float2bfloat16(v.x - __bfloat162float(h2.x));
    l2.y = __float2bfloat16(v.y - __bfloat162float(h2.y));
    __nv_bfloat16* base = A1 + row * KA1 + 2 * dp;
    *(__nv_bfloat162*)(base)        = h2;
    *(__nv_bfloat162*)(base + 1024) = h2;
    *(__nv_bfloat162*)(base + 2048) = l2;
}

// ---------------------------------------------------------------------------
// Wf1[d, col]  col = ((t*8+h)*65+f)*2 + {re,im}; pad cols [3120,3328) = 0
// ---------------------------------------------------------------------------
__global__ void build_wf1(const float* __restrict__ w_qkv)
{
    __shared__ float sw[3072];
    __shared__ float sc[128];
    __shared__ float ss[128];
    const int d = blockIdx.x;
    const int tid = threadIdx.x;

    for (int i = tid; i < 3072; i += 256)
        sw[i] = w_qkv[(size_t)d * 3072 + i];
    if (tid < 128) {
        float s, c;
        sincosf(6.2831853071795864769f * (float)tid / 128.0f, &s, &c);
        sc[tid] = c; ss[tid] = s;
    }
    __syncthreads();

    for (int p = tid; p < NP1 / 2; p += 256) {
        float re = 0.0f, im = 0.0f;
        if (p < 1560) {
            const int t = p / 520;
            const int rem = p % 520;
            const int h = rem / 65;
            const int f = rem % 65;
            const int base = t * 1024 + h * 128;
            int idx = 0;
            #pragma unroll 4
            for (int n = 0; n < 128; ++n) {
                const float w = sw[base + n];
                re += w * sc[idx];
                im -= w * ss[idx];
                idx = (idx + f) & 127;
            }
        }
        g_Wf1[(size_t)d * NP1 + 2 * p]     = re;
        g_Wf1[(size_t)d * NP1 + 2 * p + 1] = im;
    }
}

// ---------------------------------------------------------------------------
// Wf2[r, d'] (r < 1040), pad rows [1040,1152) = 0
// ---------------------------------------------------------------------------
__global__ void build_wf2(const float* __restrict__ w_out)
{
    __shared__ float coef[128];
    const int r = blockIdx.x;
    const int tid = threadIdx.x;

    if (r >= NC2) {
        #pragma unroll
        for (int j = 0; j < 4; ++j)
            g_Wf2[(size_t)r * DMODEL + tid + j * 256] = 0.0f;
        return;
    }
    const int h = r / 130;
    const int rr = r % 130;
    const int f = rr >> 1;
    const int part = rr & 1;

    if (tid < 128) {
        const int m = (f * tid) & 127;
        float s, c;
        sincosf(6.2831853071795864769f * (float)m / 128.0f, &s, &c);
        const float cf = (f == 0 || f == 64) ? 1.0f : 2.0f;
        coef[tid] = part ? (-(cf / 128.0f) * s) : ((cf / 128.0f) * c);
    }
    __syncthreads();

    float acc0 = 0.f, acc1 = 0.f, acc2 = 0.f, acc3 = 0.f;
    for (int n = 0; n < 128; ++n) {
        const float cv = coef[n];
        const float* wp = w_out + (size_t)(h * 128 + n) * DMODEL + tid;
        acc0 += cv * wp[0];
        acc1 += cv * wp[256];
        acc2 += cv * wp[512];
        acc3 += cv * wp[768];
    }
    g_Wf2[(size_t)r * DMODEL + tid]       = acc0;
    g_Wf2[(size_t)r * DMODEL + tid + 256] = acc1;
    g_Wf2[(size_t)r * DMODEL + tid + 512] = acc2;
    g_Wf2[(size_t)r * DMODEL + tid + 768] = acc3;
}

// ---------------------------------------------------------------------------
// transpose + bf16 split: src[R][C] fp32 -> dst[C][3R] = [hi | lo | hi]
// ---------------------------------------------------------------------------
__global__ void tsplit(const float* __restrict__ src, __nv_bfloat16* __restrict__ dst,
                       int R, int C)
{
    __shared__ float t[32][33];
    const int c0 = blockIdx.x * 32, r0 = blockIdx.y * 32;
    const int x = threadIdx.x, y = threadIdx.y;
    #pragma unroll
    for (int j = 0; j < 4; ++j)
        t[y + j * 8][x] = src[(size_t)(r0 + y + j * 8) * C + c0 + x];
    __syncthreads();
    #pragma unroll
    for (int j = 0; j < 4; ++j) {
        const int n = c0 + y + j * 8;
        const float v = t[x][y + j * 8];
        const __nv_bfloat16 h = __float2bfloat16(v);
        const __nv_bfloat16 l = __float2bfloat16(v - __bfloat162float(h));
        __nv_bfloat16* dp = dst + (size_t)n * (3 * R) + r0 + x;
        dp[0]     = h;
        dp[R]     = l;
        dp[2 * R] = h;
    }
}

// ---------------------------------------------------------------------------
// bf16 GEMM via mma.sync m16n8k16: C[M,N] = A[M,K] @ B[N,K]^T, fp32 out.
// BM=256, BN=128, BK=32, 512 threads (16 warps = 4m x 4n, warp tile 64x32),
// 4-stage cp.async pipeline, 80B-padded smem rows (ldmatrix conflict-free).
// ---------------------------------------------------------------------------
#define BM 256
#define BN 128
#define BK 32
#define GSTAGES 4
#define SROW 80                       // bytes per smem row (40 bf16)
#define A_ST_B (BM * SROW)            // 20480
#define B_ST_B (BN * SROW)            // 10240
#define STG_B  (A_ST_B + B_ST_B)      // 30720
#define GSMEM  (GSTAGES * STG_B)      // 122880

__global__ __launch_bounds__(512, 1)
void gemm_mma(const __nv_bfloat16* __restrict__ A,
              const __nv_bfloat16* __restrict__ B,
              float* __restrict__ C, int N, int K, int KT)
{
    extern __shared__ char smem[];
    const uint32_t sb = smem_u32(smem);

    const int tid  = threadIdx.x;
    const int warp = tid >> 5, lane = tid & 31;
    const int wm = warp >> 2, wn = warp & 3;        // 4x4 warp grid
    const size_t row0 = (size_t)blockIdx.y * BM;
    const size_t col0 = (size_t)blockIdx.x * BN;
    const __nv_bfloat16* Ag = A + row0 * (size_t)K;
    const __nv_bfloat16* Bg = B + col0 * (size_t)K;

    // per-thread cp.async mapping
    const int ar0 = tid >> 2;            // A rows tid>>2 and +128
    const int ac  = (tid & 3) * 8;       // element offset within 32-elem chunk
    const int br0 = tid >> 2;            // B row (only tid<512 -> 128 rows x4)

    float acc[4][4][4];
    #pragma unroll
    for (int i = 0; i < 4; ++i)
        #pragma unroll
        for (int j = 0; j < 4; ++j)
            #pragma unroll
            for (int q = 0; q < 4; ++q) acc[i][j][q] = 0.f;

    // prologue: stages 0..GSTAGES-2
    #pragma unroll
    for (int pc = 0; pc < GSTAGES - 1; ++pc) {
        const uint32_t st = sb + pc * STG_B;
        const int kc = pc * BK;
        cp16(st + ar0 * SROW + ac * 2,           Ag + (size_t)ar0 * K + kc + ac);
        cp16(st + (ar0 + 128) * SROW + ac * 2,   Ag + (size_t)(ar0 + 128) * K + kc + ac);
        if (br0 < BN)
            cp16(st + A_ST_B + br0 * SROW + ac * 2, Bg + (size_t)br0 * K + kc + ac);
        asm volatile("cp.async.commit_group;" ::: "memory");
    }

    // ldmatrix per-warp base addresses
    // A frag (m-tile i): row = wm*64 + i*16 + (lane&15), kk = st*16 + (lane>>4)*8
    const uint32_t a_row = (uint32_t)(wm * 64 + (lane & 15));
    const uint32_t a_kk  = (uint32_t)((lane >> 4) * 8);
    // B pair p (n-tiles 2p,2p+1): q=lane>>3; n = wn*32+(2p+(q>>1))*8+(lane&7), kk=st*16+(q&1)*8
    const int q4 = lane >> 3;
    const uint32_t b_row = (uint32_t)(wn * 32 + (q4 >> 1) * 8 + (lane & 7));
    const uint32_t b_kk  = (uint32_t)((q4 & 1) * 8);

    for (int c = 0; c < KT; ++c) {
        const uint32_t st = sb + (c % GSTAGES) * STG_B;
        asm volatile("cp.async.wait_group %0;" :: "n"(GSTAGES - 2) : "memory");
        __syncthreads();

        const int lc = c + GSTAGES - 1;
        if (lc < KT) {
            const uint32_t stn = sb + (lc % GSTAGES) * STG_B;
            const int kc = lc * BK;
            cp16(stn + ar0 * SROW + ac * 2,          Ag + (size_t)ar0 * K + kc + ac);
            cp16(stn + (ar0 + 128) * SROW + ac * 2,  Ag + (size_t)(ar0 + 128) * K + kc + ac);
            if (br0 < BN)
                cp16(stn + A_ST_B + br0 * SROW + ac * 2, Bg + (size_t)br0 * K + kc + ac);
        }
        asm volatile("cp.async.commit_group;" ::: "memory");

        #pragma unroll
        for (int kst = 0; kst < 2; ++kst) {
            uint32_t a[4][4], b[8];
            #pragma unroll
            for (int i = 0; i < 4; ++i)
                ldmx4(a[i][0], a[i][1], a[i][2], a[i][3],
                      st + (a_row + i * 16) * SROW + (kst * 16 + a_kk) * 2);
            #pragma unroll
            for (int p = 0; p < 2; ++p)
                ldmx4(b[4 * p], b[4 * p + 1], b[4 * p + 2], b[4 * p + 3],
                      st + A_ST_B + (b_row + p * 16) * SROW + (kst * 16 + b_kk) * 2);
            #pragma unroll
            for (int i = 0; i < 4; ++i)
                #pragma unroll
                for (int j = 0; j < 4; ++j)
                    mma16816(acc[i][j], a[i], &b[2 * j]);
        }
    }

    // epilogue: direct fp32 stores
    #pragma unroll
    for (int i = 0; i < 4; ++i) {
        const size_t r = row0 + wm * 64 + i * 16 + (lane >> 2);
        #pragma unroll
        for (int j = 0; j < 4; ++j) {
            const size_t cc = col0 + wn * 32 + j * 8 + (lane & 3) * 2;
            *(float2*)(C + r * N + cc)       = make_float2(acc[i][j][0], acc[i][j][1]);
            *(float2*)(C + (r + 8) * N + cc) = make_float2(acc[i][j][2], acc[i][j][3]);
        }
    }
}

// ---------------------------------------------------------------------------
// Chunked complex prefix scan; spec writes bf16-split A2 = [hi | hi | lo]
// g_F col layout: q base 0, k base 1040, v base 2080 (stride NP1)
// ---------------------------------------------------------------------------
__global__ void chunk_sum_kernel()
{
    const int c  = blockIdx.x;
    const int bh = blockIdx.y;
    const int f  = threadIdx.x;
    const int b = bh >> 3, h = bh & 7;
    const size_t rowbase = ((size_t)b * SEQ + (size_t)c * CLEN) * NP1;
    const int kc = 1040 + h * 130 + 2 * f;
    const int vc = 2080 + h * 130 + 2 * f;
    float sr = 0.f, si = 0.f;
    for (int s = 0; s < CLEN; ++s) {
        const float* p = g_F + rowbase + (size_t)s * NP1;
        const float2 Kv = *(const float2*)(p + kc);
        const float2 Vv = *(const float2*)(p + vc);
        sr += Kv.x * Vv.x - Kv.y * Vv.y;
        si += Kv.x * Vv.y + Kv.y * Vv.x;
    }
    g_CS[(bh * CHUNKS + c) * NF + f] = make_float2(sr, si);
}

__global__ void scan_off_kernel()
{
    const int bh = blockIdx.x;
    const int f  = threadIdx.x;
    float rr = 0.f, ri = 0.f;
    for (int c = 0; c < CHUNKS; ++c) {
        const int idx = (bh * CHUNKS + c) * NF + f;
        g_Off[idx] = make_float2(rr, ri);
        const float2 v = g_CS[idx];
        rr += v.x; ri += v.y;
    }
}

__global__ void spec_kernel()
{
    const int c  = blockIdx.x;
    const int bh = blockIdx.y;
    const int f  = threadIdx.x;              // 0..64
    const int b = bh >> 3, h = bh & 7;
    const size_t rbF = ((size_t)b * SEQ + (size_t)c * CLEN) * NP1;
    const size_t rbA = ((size_t)b * SEQ + (size_t)c * CLEN) * KA2;
    const int qc = h * 130 + 2 * f;
    const int kc = 1040 + qc;
    const int vc = 2080 + qc;
    float2 acc = g_Off[(bh * CHUNKS + c) * NF + f];
    for (int s = 0; s < CLEN; ++s) {
        const float* p = g_F + rbF + (size_t)s * NP1;
        const float2 Kv = *(const float2*)(p + kc);
        const float2 Vv = *(const float2*)(p + vc);
        const float2 Qv = *(const float2*)(p + qc);
        acc.x += Kv.x * Vv.x - Kv.y * Vv.y;
        acc.y += Kv.x * Vv.y + Kv.y * Vv.x;
        const float sx = acc.x * Qv.x + acc.y * Qv.y;   // acc * conj(Q)
        const float sy = acc.y * Qv.x - acc.x * Qv.y;
        __nv_bfloat162 h2, l2;
        h2.x = __float2bfloat16(sx);
        h2.y = __float2bfloat16(sy);
        l2.x = __float2bfloat16(sx - __bfloat162float(h2.x));
        l2.y = __float2bfloat16(sy - __bfloat162float(h2.y));
        __nv_bfloat16* dst = g_A2 + rbA + (size_t)s * KA2 + qc;
        *(__nv_bfloat162*)(dst)        = h2;
        *(__nv_bfloat162*)(dst + 1152) = h2;
        *(__nv_bfloat162*)(dst + 2304) = l2;
    }
}

// ---------------------------------------------------------------------------
extern "C" void kernel_launch(void* const* d_in, const int* in_sizes, int n_in,
                              void* d_out, int out_size)
{
    const float* x     = (const float*)d_in[0];
    const float* w_qkv = (const float*)d_in[1];
    const float* w_out = (const float*)d_in[2];
    float* out = (float*)d_out;

    float *pWf1, *pWf2, *pF;
    __nv_bfloat16 *pA1, *pB1, *pA2, *pB2;
    cudaGetSymbolAddress((void**)&pWf1, g_Wf1);
    cudaGetSymbolAddress((void**)&pWf2, g_Wf2);
    cudaGetSymbolAddress((void**)&pF,   g_F);
    cudaGetSymbolAddress((void**)&pA1,  g_A1);
    cudaGetSymbolAddress((void**)&pB1,  g_B1);
    cudaGetSymbolAddress((void**)&pA2,  g_A2);
    cudaGetSymbolAddress((void**)&pB2,  g_B2);

    cudaFuncSetAttribute(gemm_mma, cudaFuncAttributeMaxDynamicSharedMemorySize,
                         GSMEM);

    split_x<<<32768, 256>>>(x, pA1);
    build_wf1<<<DMODEL, 256>>>(w_qkv);
    build_wf2<<<NPAD2, 256>>>(w_out);
    tsplit<<<dim3(NP1 / 32, DMODEL / 32), dim3(32, 8)>>>(pWf1, pB1, DMODEL, NP1);
    tsplit<<<dim3(DMODEL / 32, NPAD2 / 32), dim3(32, 8)>>>(pWf2, pB2, NPAD2, DMODEL);

    // GEMM1: F = x' @ Wf1'^T   (16384 x 3328, K'=3072)
    gemm_mma<<<dim3(NP1 / BN, NROWS / BM), 512, GSMEM>>>(
        pA1, pB1, pF, NP1, KA1, KA1 / BK);

    chunk_sum_kernel<<<dim3(CHUNKS, 32), NF>>>();
    scan_off_kernel<<<32, NF>>>();
    spec_kernel<<<dim3(CHUNKS, 32), NF>>>();

    // GEMM2: out = Spec' @ Wf2'^T   (16384 x 1024, K'=3456)
    gemm_mma<<<dim3(DMODEL / BN, NROWS / BM), 512, GSMEM>>>(
        pA2, pB2, out, DMODEL, KA2, KA2 / BK);
}

// round 9
// speedup vs baseline: 2.0199x; 1.0010x over previous
#include <cuda_runtime.h>
#include <cuda_bf16.h>
#include <cstdint>

// ---------------------------------------------------------------------------
// HRR self-attention:
//   GEMM1 (mma.sync bf16 x3-split): F = x @ (W_qkv . DFT)   [fp32 out]
//   chunked complex scan: Spec = cumsum_s(Fk*Fv) * conj(Fq) -> bf16 split A2
//   GEMM2 (mma.sync bf16 x3-split): out = Spec @ (iDFT . W_out)
// tcgen05 is unavailable (harness PTX pass targets base sm_103, no 'a'
// feature set) -> use HMMA via mma.sync m16n8k16 bf16.
// ---------------------------------------------------------------------------

#define BATCH 4
#define SEQ   4096
#define DMODEL 1024
#define NHEAD 8
#define NF    65
#define NROWS 16384
#define NP1   3328          // GEMM1 N (3120 used, padded to 26*128)
#define KA1   3072          // GEMM1 K' = 3*1024
#define KA2   3456          // GEMM2 K' = 3*1152
#define NPAD2 1152
#define NC2   1040
#define CHUNKS 32
#define CLEN   128

// ---------------- scratch (static device globals; zero-initialized) --------
__device__ __align__(16) float  g_Wf1[(size_t)DMODEL * NP1];
__device__ __align__(16) float  g_Wf2[(size_t)NPAD2 * DMODEL];
__device__ __align__(16) float  g_F  [(size_t)NROWS * NP1];
__device__ __align__(16) __nv_bfloat16 g_A1[(size_t)NROWS * KA1];
__device__ __align__(16) __nv_bfloat16 g_B1[(size_t)NP1   * KA1];
__device__ __align__(16) __nv_bfloat16 g_A2[(size_t)NROWS * KA2];
__device__ __align__(16) __nv_bfloat16 g_B2[(size_t)DMODEL * KA2];
__device__ float2 g_CS [32 * CHUNKS * NF];
__device__ float2 g_Off[32 * CHUNKS * NF];

// ---------------- helpers ---------------------------------------------------
__device__ __forceinline__ uint32_t smem_u32(const void* p) {
    uint32_t a;
    asm("{ .reg .u64 t; cvta.to.shared.u64 t, %1; cvt.u32.u64 %0, t; }"
        : "=r"(a) : "l"(p));
    return a;
}
__device__ __forceinline__ void cp16(uint32_t dst, const void* src) {
    asm volatile("cp.async.cg.shared.global [%0], [%1], 16;"
                 :: "r"(dst), "l"(src) : "memory");
}
__device__ __forceinline__ void ldmx4(uint32_t& r0, uint32_t& r1,
                                      uint32_t& r2, uint32_t& r3, uint32_t a) {
    asm volatile("ldmatrix.sync.aligned.m8n8.x4.shared.b16 {%0,%1,%2,%3}, [%4];"
                 : "=r"(r0), "=r"(r1), "=r"(r2), "=r"(r3) : "r"(a));
}
__device__ __forceinline__ void mma16816(float* c, const uint32_t* a,
                                         const uint32_t* b) {
    asm volatile(
        "mma.sync.aligned.m16n8k16.row.col.f32.bf16.bf16.f32 "
        "{%0,%1,%2,%3}, {%4,%5,%6,%7}, {%8,%9}, {%0,%1,%2,%3};"
        : "+f"(c[0]), "+f"(c[1]), "+f"(c[2]), "+f"(c[3])
        : "r"(a[0]), "r"(a[1]), "r"(a[2]), "r"(a[3]), "r"(b[0]), "r"(b[1]));
}

// ---------------------------------------------------------------------------
// split x -> A1 = [x_hi | x_hi | x_lo]  (pairs with B1 = [W_hi | W_lo | W_hi])
// ---------------------------------------------------------------------------
__global__ void split_x(const float* __restrict__ x, __nv_bfloat16* __restrict__ A1)
{
    const size_t p = (size_t)blockIdx.x * 256 + threadIdx.x;   // < 16384*512
    const size_t row = p >> 9;
    const int dp = (int)(p & 511);
    const float2 v = *(const float2*)(x + row * 1024 + 2 * dp);
    __nv_bfloat162 h2, l2;
    h2.x = __float2bfloat16(v.x);
    h2.y = __float2bfloat16(v.y);
    l2.x = __float2bfloat16(v.x - __bfloat162float(h2.x));
    l2.y = __float2bfloat16(v.y - __bfloat162float(h2.y));
    __nv_bfloat16* base = A1 + row * KA1 + 2 * dp;
    *(__nv_bfloat162*)(base)        = h2;
    *(__nv_bfloat162*)(base + 1024) = h2;
    *(__nv_bfloat162*)(base + 2048) = l2;
}

// ---------------------------------------------------------------------------
// Wf1[d, col]  col = ((t*8+h)*65+f)*2 + {re,im}; pad cols [3120,3328) = 0
// ---------------------------------------------------------------------------
__global__ void build_wf1(const float* __restrict__ w_qkv)
{
    __shared__ float sw[3072];
    __shared__ float sc[128];
    __shared__ float ss[128];
    const int d = blockIdx.x;
    const int tid = threadIdx.x;

    for (int i = tid; i < 3072; i += 256)
        sw[i] = w_qkv[(size_t)d * 3072 + i];
    if (tid < 128) {
        float s, c;
        sincosf(6.2831853071795864769f * (float)tid / 128.0f, &s, &c);
        sc[tid] = c; ss[tid] = s;
    }
    __syncthreads();

    for (int p = tid; p < NP1 / 2; p += 256) {
        float re = 0.0f, im = 0.0f;
        if (p < 1560) {
            const int t = p / 520;
            const int rem = p % 520;
            const int h = rem / 65;
            const int f = rem % 65;
            const int base = t * 1024 + h * 128;
            int idx = 0;
            #pragma unroll 4
            for (int n = 0; n < 128; ++n) {
                const float w = sw[base + n];
                re += w * sc[idx];
                im -= w * ss[idx];
                idx = (idx + f) & 127;
            }
        }
        g_Wf1[(size_t)d * NP1 + 2 * p]     = re;
        g_Wf1[(size_t)d * NP1 + 2 * p + 1] = im;
    }
}

// ---------------------------------------------------------------------------
// Wf2[r, d'] (r < 1040), pad rows [1040,1152) = 0
// ---------------------------------------------------------------------------
__global__ void build_wf2(const float* __restrict__ w_out)
{
    __shared__ float coef[128];
    const int r = blockIdx.x;
    const int tid = threadIdx.x;

    if (r >= NC2) {
        #pragma unroll
        for (int j = 0; j < 4; ++j)
            g_Wf2[(size_t)r * DMODEL + tid + j * 256] = 0.0f;
        return;
    }
    const int h = r / 130;
    const int rr = r % 130;
    const int f = rr >> 1;
    const int part = rr & 1;

    if (tid < 128) {
        const int m = (f * tid) & 127;
        float s, c;
        sincosf(6.2831853071795864769f * (float)m / 128.0f, &s, &c);
        const float cf = (f == 0 || f == 64) ? 1.0f : 2.0f;
        coef[tid] = part ? (-(cf / 128.0f) * s) : ((cf / 128.0f) * c);
    }
    __syncthreads();

    float acc0 = 0.f, acc1 = 0.f, acc2 = 0.f, acc3 = 0.f;
    for (int n = 0; n < 128; ++n) {
        const float cv = coef[n];
        const float* wp = w_out + (size_t)(h * 128 + n) * DMODEL + tid;
        acc0 += cv * wp[0];
        acc1 += cv * wp[256];
        acc2 += cv * wp[512];
        acc3 += cv * wp[768];
    }
    g_Wf2[(size_t)r * DMODEL + tid]       = acc0;
    g_Wf2[(size_t)r * DMODEL + tid + 256] = acc1;
    g_Wf2[(size_t)r * DMODEL + tid + 512] = acc2;
    g_Wf2[(size_t)r * DMODEL + tid + 768] = acc3;
}

// ---------------------------------------------------------------------------
// transpose + bf16 split: src[R][C] fp32 -> dst[C][3R] = [hi | lo | hi]
// ---------------------------------------------------------------------------
__global__ void tsplit(const float* __restrict__ src, __nv_bfloat16* __restrict__ dst,
                       int R, int C)
{
    __shared__ float t[32][33];
    const int c0 = blockIdx.x * 32, r0 = blockIdx.y * 32;
    const int x = threadIdx.x, y = threadIdx.y;
    #pragma unroll
    for (int j = 0; j < 4; ++j)
        t[y + j * 8][x] = src[(size_t)(r0 + y + j * 8) * C + c0 + x];
    __syncthreads();
    #pragma unroll
    for (int j = 0; j < 4; ++j) {
        const int n = c0 + y + j * 8;
        const float v = t[x][y + j * 8];
        const __nv_bfloat16 h = __float2bfloat16(v);
        const __nv_bfloat16 l = __float2bfloat16(v - __bfloat162float(h));
        __nv_bfloat16* dp = dst + (size_t)n * (3 * R) + r0 + x;
        dp[0]     = h;
        dp[R]     = l;
        dp[2 * R] = h;
    }
}

// ---------------------------------------------------------------------------
// bf16 GEMM via mma.sync m16n8k16: C[M,N] = A[M,K] @ B[N,K]^T, fp32 out.
// BM=256, BN=128, BK=32, 512 threads (16 warps = 4m x 4n, warp tile 64x32),
// 4-stage cp.async pipeline, 80B-padded smem rows (ldmatrix conflict-free).
// ---------------------------------------------------------------------------
#define BM 256
#define BN 128
#define BK 32
#define GSTAGES 4
#define SROW 80                       // bytes per smem row (40 bf16)
#define A_ST_B (BM * SROW)            // 20480
#define B_ST_B (BN * SROW)            // 10240
#define STG_B  (A_ST_B + B_ST_B)      // 30720
#define GSMEM  (GSTAGES * STG_B)      // 122880

__global__ __launch_bounds__(512, 1)
void gemm_mma(const __nv_bfloat16* __restrict__ A,
              const __nv_bfloat16* __restrict__ B,
              float* __restrict__ C, int N, int K, int KT)
{
    extern __shared__ char smem[];
    const uint32_t sb = smem_u32(smem);

    const int tid  = threadIdx.x;
    const int warp = tid >> 5, lane = tid & 31;
    const int wm = warp >> 2, wn = warp & 3;        // 4x4 warp grid
    const size_t row0 = (size_t)blockIdx.y * BM;
    const size_t col0 = (size_t)blockIdx.x * BN;
    const __nv_bfloat16* Ag = A + row0 * (size_t)K;
    const __nv_bfloat16* Bg = B + col0 * (size_t)K;

    // per-thread cp.async mapping
    const int ar0 = tid >> 2;            // A rows tid>>2 and +128
    const int ac  = (tid & 3) * 8;       // element offset within 32-elem chunk
    const int br0 = tid >> 2;            // B row (only tid<512 -> 128 rows x4)

    float acc[4][4][4];
    #pragma unroll
    for (int i = 0; i < 4; ++i)
        #pragma unroll
        for (int j = 0; j < 4; ++j)
            #pragma unroll
            for (int q = 0; q < 4; ++q) acc[i][j][q] = 0.f;

    // prologue: stages 0..GSTAGES-2
    #pragma unroll
    for (int pc = 0; pc < GSTAGES - 1; ++pc) {
        const uint32_t st = sb + pc * STG_B;
        const int kc = pc * BK;
        cp16(st + ar0 * SROW + ac * 2,           Ag + (size_t)ar0 * K + kc + ac);
        cp16(st + (ar0 + 128) * SROW + ac * 2,   Ag + (size_t)(ar0 + 128) * K + kc + ac);
        if (br0 < BN)
            cp16(st + A_ST_B + br0 * SROW + ac * 2, Bg + (size_t)br0 * K + kc + ac);
        asm volatile("cp.async.commit_group;" ::: "memory");
    }

    // ldmatrix per-warp base addresses
    // A frag (m-tile i): row = wm*64 + i*16 + (lane&15), kk = st*16 + (lane>>4)*8
    const uint32_t a_row = (uint32_t)(wm * 64 + (lane & 15));
    const uint32_t a_kk  = (uint32_t)((lane >> 4) * 8);
    // B pair p (n-tiles 2p,2p+1): q=lane>>3; n = wn*32+(2p+(q>>1))*8+(lane&7), kk=st*16+(q&1)*8
    const int q4 = lane >> 3;
    const uint32_t b_row = (uint32_t)(wn * 32 + (q4 >> 1) * 8 + (lane & 7));
    const uint32_t b_kk  = (uint32_t)((q4 & 1) * 8);

    for (int c = 0; c < KT; ++c) {
        const uint32_t st = sb + (c % GSTAGES) * STG_B;
        asm volatile("cp.async.wait_group %0;" :: "n"(GSTAGES - 2) : "memory");
        __syncthreads();

        const int lc = c + GSTAGES - 1;
        if (lc < KT) {
            const uint32_t stn = sb + (lc % GSTAGES) * STG_B;
            const int kc = lc * BK;
            cp16(stn + ar0 * SROW + ac * 2,          Ag + (size_t)ar0 * K + kc + ac);
            cp16(stn + (ar0 + 128) * SROW + ac * 2,  Ag + (size_t)(ar0 + 128) * K + kc + ac);
            if (br0 < BN)
                cp16(stn + A_ST_B + br0 * SROW + ac * 2, Bg + (size_t)br0 * K + kc + ac);
        }
        asm volatile("cp.async.commit_group;" ::: "memory");

        #pragma unroll
        for (int kst = 0; kst < 2; ++kst) {
            uint32_t a[4][4], b[8];
            #pragma unroll
            for (int i = 0; i < 4; ++i)
                ldmx4(a[i][0], a[i][1], a[i][2], a[i][3],
                      st + (a_row + i * 16) * SROW + (kst * 16 + a_kk) * 2);
            #pragma unroll
            for (int p = 0; p < 2; ++p)
                ldmx4(b[4 * p], b[4 * p + 1], b[4 * p + 2], b[4 * p + 3],
                      st + A_ST_B + (b_row + p * 16) * SROW + (kst * 16 + b_kk) * 2);
            #pragma unroll
            for (int i = 0; i < 4; ++i)
                #pragma unroll
                for (int j = 0; j < 4; ++j)
                    mma16816(acc[i][j], a[i], &b[2 * j]);
        }
    }

    // epilogue: direct fp32 stores
    #pragma unroll
    for (int i = 0; i < 4; ++i) {
        const size_t r = row0 + wm * 64 + i * 16 + (lane >> 2);
        #pragma unroll
        for (int j = 0; j < 4; ++j) {
            const size_t cc = col0 + wn * 32 + j * 8 + (lane & 3) * 2;
            *(float2*)(C + r * N + cc)       = make_float2(acc[i][j][0], acc[i][j][1]);
            *(float2*)(C + (r + 8) * N + cc) = make_float2(acc[i][j][2], acc[i][j][3]);
        }
    }
}

// ---------------------------------------------------------------------------
// Chunked complex prefix scan; spec writes bf16-split A2 = [hi | hi | lo]
// g_F col layout: q base 0, k base 1040, v base 2080 (stride NP1)
// ---------------------------------------------------------------------------
__global__ void chunk_sum_kernel()
{
    const int c  = blockIdx.x;
    const int bh = blockIdx.y;
    const int f  = threadIdx.x;
    const int b = bh >> 3, h = bh & 7;
    const size_t rowbase = ((size_t)b * SEQ + (size_t)c * CLEN) * NP1;
    const int kc = 1040 + h * 130 + 2 * f;
    const int vc = 2080 + h * 130 + 2 * f;
    float sr = 0.f, si = 0.f;
    for (int s = 0; s < CLEN; ++s) {
        const float* p = g_F + rowbase + (size_t)s * NP1;
        const float2 Kv = *(const float2*)(p + kc);
        const float2 Vv = *(const float2*)(p + vc);
        sr += Kv.x * Vv.x - Kv.y * Vv.y;
        si += Kv.x * Vv.y + Kv.y * Vv.x;
    }
    g_CS[(bh * CHUNKS + c) * NF + f] = make_float2(sr, si);
}

__global__ void scan_off_kernel()
{
    const int bh = blockIdx.x;
    const int f  = threadIdx.x;
    float rr = 0.f, ri = 0.f;
    for (int c = 0; c < CHUNKS; ++c) {
        const int idx = (bh * CHUNKS + c) * NF + f;
        g_Off[idx] = make_float2(rr, ri);
        const float2 v = g_CS[idx];
        rr += v.x; ri += v.y;
    }
}

__global__ void spec_kernel()
{
    const int c  = blockIdx.x;
    const int bh = blockIdx.y;
    const int f  = threadIdx.x;              // 0..64
    const int b = bh >> 3, h = bh & 7;
    const size_t rbF = ((size_t)b * SEQ + (size_t)c * CLEN) * NP1;
    const size_t rbA = ((size_t)b * SEQ + (size_t)c * CLEN) * KA2;
    const int qc = h * 130 + 2 * f;
    const int kc = 1040 + qc;
    const int vc = 2080 + qc;
    float2 acc = g_Off[(bh * CHUNKS + c) * NF + f];
    for (int s = 0; s < CLEN; ++s) {
        const float* p = g_F + rbF + (size_t)s * NP1;
        const float2 Kv = *(const float2*)(p + kc);
        const float2 Vv = *(const float2*)(p + vc);
        const float2 Qv = *(const float2*)(p + qc);
        acc.x += Kv.x * Vv.x - Kv.y * Vv.y;
        acc.y += Kv.x * Vv.y + Kv.y * Vv.x;
        const float sx = acc.x * Qv.x + acc.y * Qv.y;   // acc * conj(Q)
        const float sy = acc.y * Qv.x - acc.x * Qv.y;
        __nv_bfloat162 h2, l2;
        h2.x = __float2bfloat16(sx);
        h2.y = __float2bfloat16(sy);
        l2.x = __float2bfloat16(sx - __bfloat162float(h2.x));
        l2.y = __float2bfloat16(sy - __bfloat162float(h2.y));
        __nv_bfloat16* dst = g_A2 + rbA + (size_t)s * KA2 + qc;
        *(__nv_bfloat162*)(dst)        = h2;
        *(__nv_bfloat162*)(dst + 1152) = h2;
        *(__nv_bfloat162*)(dst + 2304) = l2;
    }
}

// ---------------------------------------------------------------------------
extern "C" void kernel_launch(void* const* d_in, const int* in_sizes, int n_in,
                              void* d_out, int out_size)
{
    const float* x     = (const float*)d_in[0];
    const float* w_qkv = (const float*)d_in[1];
    const float* w_out = (const float*)d_in[2];
    float* out = (float*)d_out;

    float *pWf1, *pWf2, *pF;
    __nv_bfloat16 *pA1, *pB1, *pA2, *pB2;
    cudaGetSymbolAddress((void**)&pWf1, g_Wf1);
    cudaGetSymbolAddress((void**)&pWf2, g_Wf2);
    cudaGetSymbolAddress((void**)&pF,   g_F);
    cudaGetSymbolAddress((void**)&pA1,  g_A1);
    cudaGetSymbolAddress((void**)&pB1,  g_B1);
    cudaGetSymbolAddress((void**)&pA2,  g_A2);
    cudaGetSymbolAddress((void**)&pB2,  g_B2);

    cudaFuncSetAttribute(gemm_mma, cudaFuncAttributeMaxDynamicSharedMemorySize,
                         GSMEM);

    split_x<<<32768, 256>>>(x, pA1);
    build_wf1<<<DMODEL, 256>>>(w_qkv);
    build_wf2<<<NPAD2, 256>>>(w_out);
    tsplit<<<dim3(NP1 / 32, DMODEL / 32), dim3(32, 8)>>>(pWf1, pB1, DMODEL, NP1);
    tsplit<<<dim3(DMODEL / 32, NPAD2 / 32), dim3(32, 8)>>>(pWf2, pB2, NPAD2, DMODEL);

    // GEMM1: F = x' @ Wf1'^T   (16384 x 3328, K'=3072)
    gemm_mma<<<dim3(NP1 / BN, NROWS / BM), 512, GSMEM>>>(
        pA1, pB1, pF, NP1, KA1, KA1 / BK);

    chunk_sum_kernel<<<dim3(CHUNKS, 32), NF>>>();
    scan_off_kernel<<<32, NF>>>();
    spec_kernel<<<dim3(CHUNKS, 32), NF>>>();

    // GEMM2: out = Spec' @ Wf2'^T   (16384 x 1024, K'=3456)
    gemm_mma<<<dim3(DMODEL / BN, NROWS / BM), 512, GSMEM>>>(
        pA2, pB2, out, DMODEL, KA2, KA2 / BK);
}